// round 6
// baseline (speedup 1.0000x reference)
#include <cuda_runtime.h>
#include <cuda_bf16.h>
#include <math.h>

// ---------------------------------------------------------------------------
// CompactHash — R6: hybrid layout (full-line loads + single-pass hashing).
//  lane = (corner_xy[2b], probe_pair[3b]); each lane serves 2 corners
//  (bz=0 and bz=1). Per level:
//    embA/embB: float4, 8 lanes cover each corner's full 128B line -> 4 wf ea.
//    cbA/cbB:   float2, 8 lanes cover each cb row's 64B            -> 4 wf ea.
//  = 16 L1 wavefronts/level (fp32 floor). Hashes share (bx,by) products:
//  4 IMAD + 2 IADD + 4 LOP3 per level for all four hash values.
// ---------------------------------------------------------------------------

#define NUM_LEVELS   8
#define PROBE        16
#define INDEX_PARAMS 16384
#define TOTAL_CB_ROWS (NUM_LEVELS * INDEX_PARAMS)   // 131072
#define BATCH        524288

// 8 MB scratch for normalized codebook (device global: no allocation APIs).
__device__ float g_cbnorm[TOTAL_CB_ROWS * PROBE];

__constant__ int c_level_off[NUM_LEVELS] =
    {0, 4096, 36864, 299008, 823296, 1347584, 1871872, 2396160};

// -------------------------------- softmax prologue -------------------------
__global__ void __launch_bounds__(256)
softmax_cb_kernel(const float* __restrict__ cb)
{
    int row = blockIdx.x * blockDim.x + threadIdx.x;   // 0 .. 131071
    const float4* src = reinterpret_cast<const float4*>(cb + (size_t)row * PROBE);
    float4 v0 = __ldg(src + 0);
    float4 v1 = __ldg(src + 1);
    float4 v2 = __ldg(src + 2);
    float4 v3 = __ldg(src + 3);

    float e[16];
    // codebook values are tiny (|x| < 0.01): no max-subtraction needed.
    e[0]  = __expf(v0.x); e[1]  = __expf(v0.y); e[2]  = __expf(v0.z); e[3]  = __expf(v0.w);
    e[4]  = __expf(v1.x); e[5]  = __expf(v1.y); e[6]  = __expf(v1.z); e[7]  = __expf(v1.w);
    e[8]  = __expf(v2.x); e[9]  = __expf(v2.y); e[10] = __expf(v2.z); e[11] = __expf(v2.w);
    e[12] = __expf(v3.x); e[13] = __expf(v3.y); e[14] = __expf(v3.z); e[15] = __expf(v3.w);

    float s = 0.f;
#pragma unroll
    for (int i = 0; i < 16; i++) s += e[i];
    float inv = __fdividef(1.f, s);

    float4* dst = reinterpret_cast<float4*>(g_cbnorm + (size_t)row * PROBE);
    dst[0] = make_float4(e[0]*inv,  e[1]*inv,  e[2]*inv,  e[3]*inv);
    dst[1] = make_float4(e[4]*inv,  e[5]*inv,  e[6]*inv,  e[7]*inv);
    dst[2] = make_float4(e[8]*inv,  e[9]*inv,  e[10]*inv, e[11]*inv);
    dst[3] = make_float4(e[12]*inv, e[13]*inv, e[14]*inv, e[15]*inv);
}

// -------------------------------- main kernel ------------------------------
__global__ void __launch_bounds__(256, 4)
compact_hash_kernel(const float*  __restrict__ inp,   // [BATCH,3]
                    const float2* __restrict__ emb,   // [TOTAL_EMB] rows of 2
                    float*        __restrict__ out)   // [BATCH,16]
{
    const int warp = (blockIdx.x * blockDim.x + threadIdx.x) >> 5;  // point id
    const int lane = threadIdx.x & 31;
    const unsigned bx = (lane >> 3) & 1;   // corner x-bit (shared by both corners)
    const unsigned by = (lane >> 4) & 1;   // corner y-bit (shared)
    const int      pp = lane & 7;          // probe pair (rows 2pp, 2pp+1)

    const float px = __ldg(inp + warp * 3 + 0);
    const float py = __ldg(inp + warp * 3 + 1);
    const float pz = __ldg(inp + warp * 3 + 2);

    float v[16];   // v[2L] = comp0 partial of level L, v[2L+1] = comp1
#pragma unroll
    for (int i = 0; i < 16; i++) v[i] = 0.f;

#pragma unroll
    for (int L = 0; L < NUM_LEVELS; L++) {
        const float    res = (float)(16 << L);
        const int      lp  = (12 + 3 * L < 19) ? (12 + 3 * L) : 19;
        const unsigned pm  = (1u << lp) - 1u;

        const float fx = px * res, fy = py * res, fz = pz * res;
        const float ix = floorf(fx), iy = floorf(fy), iz = floorf(fz);
        const float xf = fx - ix,    yf = fy - iy,    zf = fz - iz;

        // hashes for both corners (prime for dim 0 is 1)
        const unsigned xs  = (unsigned)(int)ix + bx;
        const unsigned yb  = (unsigned)(int)iy + by;
        const unsigned ym1 = yb * 2654435761u;
        const unsigned ym2 = yb * 2654435767u;
        const unsigned zm1 = (unsigned)(int)iz * 805459861u;
        const unsigned zm2 = (unsigned)(int)iz * 805459871u;
        const unsigned h1a = xs ^ ym1 ^ zm1;               // bz = 0
        const unsigned h1b = xs ^ ym1 ^ (zm1 + 805459861u); // bz = 1
        const unsigned h2a = xs ^ ym2 ^ zm2;
        const unsigned h2b = xs ^ ym2 ^ (zm2 + 805459871u);

        const unsigned baseA = (h1a << 4) & pm;
        const unsigned baseB = (h1b << 4) & pm;
        const unsigned crA   = h2a & (INDEX_PARAMS - 1u);
        const unsigned crB   = h2b & (INDEX_PARAMS - 1u);

        // trilinear weights
        const float wxy = (bx ? xf : 1.f - xf) * (by ? yf : 1.f - yf);
        const float wtA = wxy * (1.f - zf);
        const float wtB = wxy * zf;

        const float4* __restrict__ embL =
            reinterpret_cast<const float4*>(emb + c_level_off[L]);
        const float2* __restrict__ cbL =
            reinterpret_cast<const float2*>(g_cbnorm) + ((size_t)L << 17) + pp;

        // corner A (bz=0): rows 2pp, 2pp+1 -> 8 lanes cover full 128B line
        const float4 ea = __ldg(embL + (baseA >> 1) + pp);
        const float2 wa = __ldg(cbL + crA * (PROBE / 2));
        // corner B (bz=1)
        const float4 eb = __ldg(embL + (baseB >> 1) + pp);
        const float2 wb = __ldg(cbL + crB * (PROBE / 2));

        float sa0 = wa.x * ea.x;
        float sa1 = wa.x * ea.y;
        sa0 = fmaf(wa.y, ea.z, sa0);
        sa1 = fmaf(wa.y, ea.w, sa1);
        float sb0 = wb.x * eb.x;
        float sb1 = wb.x * eb.y;
        sb0 = fmaf(wb.y, eb.z, sb0);
        sb1 = fmaf(wb.y, eb.w, sb1);

        v[2*L]   = fmaf(wtA, sa0, fmaf(wtB, sb0, v[2*L]));
        v[2*L+1] = fmaf(wtA, sa1, fmaf(wtB, sb1, v[2*L+1]));
    }

    // ---- multi-value butterfly reduction: 16 values over 32 lanes ----
    // Stages route value-bit b to lane-bit b (masks 1,2,4,8), then mask 16
    // final-reduces. Afterwards lane l holds feature (l & 15) summed over
    // all 32 lanes.
    float t8[8];
#pragma unroll
    for (int k = 0; k < 8; k++) {
        const float lo = v[2*k], hi = v[2*k+1];
        const float send = (lane & 1) ? lo : hi;
        const float recv = __shfl_xor_sync(0xffffffffu, send, 1);
        t8[k] = ((lane & 1) ? hi : lo) + recv;
    }
    float t4[4];
#pragma unroll
    for (int k = 0; k < 4; k++) {
        const float lo = t8[2*k], hi = t8[2*k+1];
        const float send = (lane & 2) ? lo : hi;
        const float recv = __shfl_xor_sync(0xffffffffu, send, 2);
        t4[k] = ((lane & 2) ? hi : lo) + recv;
    }
    float t2[2];
#pragma unroll
    for (int k = 0; k < 2; k++) {
        const float lo = t4[2*k], hi = t4[2*k+1];
        const float send = (lane & 4) ? lo : hi;
        const float recv = __shfl_xor_sync(0xffffffffu, send, 4);
        t2[k] = ((lane & 4) ? hi : lo) + recv;
    }
    float t1;
    {
        const float lo = t2[0], hi = t2[1];
        const float send = (lane & 8) ? lo : hi;
        const float recv = __shfl_xor_sync(0xffffffffu, send, 8);
        t1 = ((lane & 8) ? hi : lo) + recv;
    }
    const float r = t1 + __shfl_xor_sync(0xffffffffu, t1, 16);

    if (lane < 16) out[(size_t)warp * 16 + lane] = r;
}

// -------------------------------- launcher ---------------------------------
extern "C" void kernel_launch(void* const* d_in, const int* in_sizes, int n_in,
                              void* d_out, int out_size)
{
    const float*  inputs     = (const float*)d_in[0];   // [524288, 3]
    const float2* embeddings = (const float2*)d_in[1];  // [2920448, 2]
    const float*  code_book  = (const float*)d_in[2];   // [131072, 16]
    float*        out        = (float*)d_out;           // [524288, 16]

    softmax_cb_kernel<<<TOTAL_CB_ROWS / 256, 256>>>(code_book);
    compact_hash_kernel<<<BATCH / 8, 256>>>(inputs, embeddings, out);
}